// round 2
// baseline (speedup 1.0000x reference)
#include <cuda_runtime.h>
#include <math.h>

// ----------------------------------------------------------------------------
// Single persistent-kernel implementation.
// Net: x = 2*in-1; out1 = long_conv(x); out2 = long_conv(out1);
// return interp128(sigmoid(out2)).  Looper branch is deterministically one
// iteration (lc_values == 3.0) and does not touch output values -> skipped.
// Only the sparse positions actually consumed are ever evaluated.
// Phases chained with a software grid barrier (148 blocks, co-resident).
// ----------------------------------------------------------------------------

#define NB  148
#define NT  256
#define NIN 1024          // input H=W
#define HC1 510           // conv(1024) s2 k5 VALID
#define HC2 1022          // conv(2047) s2 k5 VALID
#define N1  2047          // out1 H=W
#define N2  4093          // out2 H=W

__device__ float    g_key[2][3072];
__device__ float    g_dots[2][112];
__device__ float    g_kern[2][232];
__device__ unsigned g_count;   // barrier arrivals (monotone within a launch)
__device__ unsigned g_done;    // end-of-kernel arrivals (for counter reset)

__device__ __forceinline__ float sigf(float v) { return 1.f / (1.f + __expf(-v)); }

__device__ __forceinline__ void gbar(unsigned phase) {
    __syncthreads();
    if (threadIdx.x == 0) {
        __threadfence();
        atomicAdd(&g_count, 1u);
        const unsigned tgt = phase * NB;
        while (*((volatile unsigned*)&g_count) < tgt) { }
        __threadfence();
    }
    __syncthreads();
}

// out1[*, oh, ow] for all 3 output channels. conv_transpose(x', kern, s2, p2, k5):
// tap valid when (oh+2-kh) even and row in range.  x' = 2x-1 inline.
__device__ __forceinline__ void out1_val3(const float* __restrict__ x,
                                          const float* __restrict__ kk,
                                          int oh, int ow, float r[3]) {
    r[0] = 0.f; r[1] = 0.f; r[2] = 0.f;
#pragma unroll
    for (int kh = 0; kh < 5; ++kh) {
        int t = oh + 2 - kh;
        if (t & 1) continue;
        unsigned i = (unsigned)(t >> 1);
        if (i >= (unsigned)NIN) continue;
#pragma unroll
        for (int kw = 0; kw < 5; ++kw) {
            int u = ow + 2 - kw;
            if (u & 1) continue;
            unsigned j = (unsigned)(u >> 1);
            if (j >= (unsigned)NIN) continue;
            const float* xp = x + i * NIN + j;
            float x0 = 2.f * xp[0]             - 1.f;
            float x1 = 2.f * xp[NIN * NIN]     - 1.f;
            float x2 = 2.f * xp[2 * NIN * NIN] - 1.f;
            int ki = kh * 5 + kw;
#pragma unroll
            for (int oc = 0; oc < 3; ++oc)   // kern[ic,oc,kh,kw] = kk[ic*75+oc*25+ki]
                r[oc] += x0 * kk[oc * 25 + ki]
                       + x1 * kk[75  + oc * 25 + ki]
                       + x2 * kk[150 + oc * 25 + ki];
        }
    }
}

__global__ void __launch_bounds__(NT, 1)
fused_net(const float* __restrict__ x, const float* __restrict__ w,
          const float* __restrict__ b, const float* __restrict__ keys,
          const float* __restrict__ values, float* __restrict__ out)
{
    __shared__ float sk1[232];
    __shared__ float sk2[232];
    __shared__ float sred[NT / 32];
    __shared__ float satt[104];
    __shared__ float sinv;

    const int tid  = threadIdx.x;
    const int bid  = blockIdx.x;
    const int gtid = bid * NT + tid;

    // ---- Phase 1: key1 = sigmoid(conv2d_s2(x')) at 32x32 sampled positions --
    if (gtid < 3072) {
        int oc = gtid >> 10, rem = gtid & 1023;
        int sr = rem >> 5, sc = rem & 31;
        int r0 = 2 * ((sr * HC1) >> 5);
        int c0 = 2 * ((sc * HC1) >> 5);
        float acc = b[oc];
#pragma unroll
        for (int ic = 0; ic < 3; ++ic) {
            const float* xp = x + ic * NIN * NIN + r0 * NIN + c0;
            const float* wp = w + oc * 75 + ic * 25;
#pragma unroll
            for (int kh = 0; kh < 5; ++kh)
#pragma unroll
                for (int kw = 0; kw < 5; ++kw)
                    acc += (2.f * xp[kh * NIN + kw] - 1.f) * wp[kh * 5 + kw];
        }
        g_key[0][gtid] = sigf(acc);
    }
    gbar(1);

    // ---- Phase 2: dots1[row] = keys[row] . key1 (one block per row) ---------
    if (bid < 100) {
        float p = 0.f;
        const float* kr = keys + bid * 3072;
        for (int k = tid; k < 3072; k += NT)
            p += kr[k] * __ldcg(&g_key[0][k]);
#pragma unroll
        for (int o = 16; o; o >>= 1) p += __shfl_down_sync(0xffffffffu, p, o);
        if ((tid & 31) == 0) sred[tid >> 5] = p;
        __syncthreads();
        if (tid == 0) {
            float s = 0.f;
#pragma unroll
            for (int i = 0; i < NT / 32; ++i) s += sred[i];
            g_dots[0][bid] = s;
        }
    }
    gbar(2);

    // ---- Phase 3: combine1 (block 0): softmax(dots1) @ values -> kern1 ------
    if (bid == 0) {
        if (tid < 100) satt[tid] = __ldcg(&g_dots[0][tid]);
        __syncthreads();
        if (tid == 0) {
            float m = satt[0];
            for (int i = 1; i < 100; ++i) m = fmaxf(m, satt[i]);
            float s = 0.f;
            for (int i = 0; i < 100; ++i) { float e = __expf(satt[i] - m); satt[i] = e; s += e; }
            sinv = 1.f / s;
        }
        __syncthreads();
        if (tid < 225) {
            float acc = 0.f;
            for (int i = 0; i < 100; ++i) acc += satt[i] * values[i * 225 + tid];
            g_kern[0][tid] = acc * sinv;
        }
    }
    gbar(3);

    // ---- Phase 4: fused o1win + key2 (one warp per sampled conv window) -----
    if (tid < 225) sk1[tid] = __ldcg(&g_kern[0][tid]);
    __syncthreads();
    {
        const int gw   = bid * (NT / 32) + (tid >> 5);
        const int lane = tid & 31;
        if (gw < 1024) {
            const int sr = gw >> 5, sc = gw & 31;
            float p0 = 0.f, p1 = 0.f, p2 = 0.f;
            if (lane < 25) {
                const int kh = lane / 5, kw = lane - kh * 5;
                const int oh = 2 * ((sr * HC2) >> 5) + kh;
                const int ow = 2 * ((sc * HC2) >> 5) + kw;
                float rr[3];
                out1_val3(x, sk1, oh, ow, rr);
                const int ki = kh * 5 + kw;
#pragma unroll
                for (int c1 = 0; c1 < 3; ++c1) {
                    p0 += rr[c1] * w[c1 * 25 + ki];          // oc=0: w[0*75+c1*25+ki]
                    p1 += rr[c1] * w[75  + c1 * 25 + ki];
                    p2 += rr[c1] * w[150 + c1 * 25 + ki];
                }
            }
#pragma unroll
            for (int o = 16; o; o >>= 1) {
                p0 += __shfl_down_sync(0xffffffffu, p0, o);
                p1 += __shfl_down_sync(0xffffffffu, p1, o);
                p2 += __shfl_down_sync(0xffffffffu, p2, o);
            }
            if (lane == 0) {
                const int idx = sr * 32 + sc;
                g_key[1][idx]        = sigf(p0 + b[0]);
                g_key[1][1024 + idx] = sigf(p1 + b[1]);
                g_key[1][2048 + idx] = sigf(p2 + b[2]);
            }
        }
    }
    gbar(4);

    // ---- Phase 5: dots2 -----------------------------------------------------
    if (bid < 100) {
        float p = 0.f;
        const float* kr = keys + bid * 3072;
        for (int k = tid; k < 3072; k += NT)
            p += kr[k] * __ldcg(&g_key[1][k]);
#pragma unroll
        for (int o = 16; o; o >>= 1) p += __shfl_down_sync(0xffffffffu, p, o);
        if ((tid & 31) == 0) sred[tid >> 5] = p;
        __syncthreads();
        if (tid == 0) {
            float s = 0.f;
#pragma unroll
            for (int i = 0; i < NT / 32; ++i) s += sred[i];
            g_dots[1][bid] = s;
        }
    }
    gbar(5);

    // ---- Phase 6: combine2 --------------------------------------------------
    if (bid == 0) {
        if (tid < 100) satt[tid] = __ldcg(&g_dots[1][tid]);
        __syncthreads();
        if (tid == 0) {
            float m = satt[0];
            for (int i = 1; i < 100; ++i) m = fmaxf(m, satt[i]);
            float s = 0.f;
            for (int i = 0; i < 100; ++i) { float e = __expf(satt[i] - m); satt[i] = e; s += e; }
            sinv = 1.f / s;
        }
        __syncthreads();
        if (tid < 225) {
            float acc = 0.f;
            for (int i = 0; i < 100; ++i) acc += satt[i] * values[i * 225 + tid];
            g_kern[1][tid] = acc * sinv;
        }
    }
    gbar(6);

    // ---- Phase 7: final = interp128(sigmoid(conv_transpose(out1, kern2))) ---
    if (tid < 225) { sk1[tid] = __ldcg(&g_kern[0][tid]); sk2[tid] = __ldcg(&g_kern[1][tid]); }
    __syncthreads();
    if (gtid < 16384) {
        const int r = gtid >> 7, c = gtid & 127;
        const int R = (r * N2) >> 7;
        const int C = (c * N2) >> 7;
        float a0 = 0.f, a1 = 0.f, a2 = 0.f;
#pragma unroll
        for (int kh = 0; kh < 5; ++kh) {
            int t = R + 2 - kh;
            if (t & 1) continue;
            unsigned i2 = (unsigned)(t >> 1);
            if (i2 >= (unsigned)N1) continue;
#pragma unroll
            for (int kw = 0; kw < 5; ++kw) {
                int u = C + 2 - kw;
                if (u & 1) continue;
                unsigned j2 = (unsigned)(u >> 1);
                if (j2 >= (unsigned)N1) continue;
                float ov[3];
                out1_val3(x, sk1, (int)i2, (int)j2, ov);
                const int ki = kh * 5 + kw;
                a0 += ov[0] * sk2[ki]      + ov[1] * sk2[75 + ki]  + ov[2] * sk2[150 + ki];
                a1 += ov[0] * sk2[25 + ki] + ov[1] * sk2[100 + ki] + ov[2] * sk2[175 + ki];
                a2 += ov[0] * sk2[50 + ki] + ov[1] * sk2[125 + ki] + ov[2] * sk2[200 + ki];
            }
        }
        out[gtid]             = sigf(a0);
        out[16384 + gtid]     = sigf(a1);
        out[2 * 16384 + gtid] = sigf(a2);
    }

    // ---- Counter reset so the graph replays from clean state ----------------
    if (tid == 0) {
        __threadfence();
        unsigned d = atomicAdd(&g_done, 1u) + 1u;
        if (d == NB) { g_count = 0; g_done = 0; __threadfence(); }
    }
}

extern "C" void kernel_launch(void* const* d_in, const int* in_sizes, int n_in,
                              void* d_out, int out_size) {
    (void)in_sizes; (void)n_in; (void)out_size;
    const float* x      = (const float*)d_in[0];  // [1,3,1024,1024]
    const float* w      = (const float*)d_in[1];  // lk1_conv_w [3,3,5,5]
    const float* b      = (const float*)d_in[2];  // lk1_conv_b [3]
    const float* keys   = (const float*)d_in[3];  // lk1_keys [100,3072]
    const float* values = (const float*)d_in[4];  // lk1_values [100,225]
    float* out = (float*)d_out;                   // [1,3,128,128] float32

    fused_net<<<NB, NT>>>(x, w, b, keys, values, out);
}